// round 6
// baseline (speedup 1.0000x reference)
#include <cuda_runtime.h>
#include <cuda_bf16.h>
#include <cstdint>

#define NROWS 100000
#define SDIM  1024
#define DDIM  512
#define NRBF  8
#define FEAT  20
#define GPITCH 21

// dynamic smem: C double buffer only
#define SM_C_FLOATS 8192
#define DSMEM_BYTES (2 * SM_C_FLOATS * 4)    // 65536

__device__ float g_G[FEAT * FEAT];
__device__ float g_H[FEAT];
__device__ float g_Wbar[FEAT];
__device__ float g_S[2];

__device__ __forceinline__ void cp16(void* dst, const void* src) {
    unsigned d = (unsigned)__cvta_generic_to_shared(dst);
    asm volatile("cp.async.cg.shared.global [%0], [%1], 16;" :: "r"(d), "l"(src));
}
__device__ __forceinline__ uint64_t packf2(float lo, float hi) {
    uint64_t r;
    asm("mov.b64 %0, {%1, %2};" : "=l"(r) : "f"(lo), "f"(hi));
    return r;
}

// ============================================================
// K0: warp-per-item precompute (421 items)
// ============================================================
__global__ void k0_precompute(const float* __restrict__ W,
                              const float* __restrict__ b)
{
    const int lane = threadIdx.x & 31;
    const int item = (blockIdx.x * blockDim.x + threadIdx.x) >> 5;
    const float invD = 1.0f / DDIM;

    if (item < FEAT * FEAT) {
        const int l = item / FEAT, m = item % FEAT;
        const float4* wl = reinterpret_cast<const float4*>(W + l * DDIM);
        const float4* wm = reinterpret_cast<const float4*>(W + m * DDIM);
        float s = 0.f;
#pragma unroll
        for (int k = 0; k < 4; k++) {
            const float4 a = wl[lane + 32 * k];
            const float4 c = wm[lane + 32 * k];
            s = fmaf(a.x, c.x, fmaf(a.y, c.y, fmaf(a.z, c.z, fmaf(a.w, c.w, s))));
        }
#pragma unroll
        for (int o = 16; o; o >>= 1) s += __shfl_xor_sync(0xffffffffu, s, o);
        if (lane == 0) g_G[item] = s * invD;
    } else if (item < FEAT * FEAT + FEAT) {
        const int l = item - FEAT * FEAT;
        const float4* wl = reinterpret_cast<const float4*>(W + l * DDIM);
        const float4* bp = reinterpret_cast<const float4*>(b);
        float h = 0.f, wb = 0.f;
#pragma unroll
        for (int k = 0; k < 4; k++) {
            const float4 a = wl[lane + 32 * k];
            const float4 c = bp[lane + 32 * k];
            h  = fmaf(a.x, c.x, fmaf(a.y, c.y, fmaf(a.z, c.z, fmaf(a.w, c.w, h))));
            wb += (a.x + a.y) + (a.z + a.w);
        }
#pragma unroll
        for (int o = 16; o; o >>= 1) {
            h  += __shfl_xor_sync(0xffffffffu, h,  o);
            wb += __shfl_xor_sync(0xffffffffu, wb, o);
        }
        if (lane == 0) { g_H[l] = h * invD; g_Wbar[l] = wb * invD; }
    } else if (item == FEAT * FEAT + FEAT) {
        const float4* bp = reinterpret_cast<const float4*>(b);
        float bb = 0.f, b2 = 0.f;
#pragma unroll
        for (int k = 0; k < 4; k++) {
            const float4 c = bp[lane + 32 * k];
            bb += (c.x + c.y) + (c.z + c.w);
            b2  = fmaf(c.x, c.x, fmaf(c.y, c.y, fmaf(c.z, c.z, fmaf(c.w, c.w, b2))));
        }
#pragma unroll
        for (int o = 16; o; o >>= 1) {
            bb += __shfl_xor_sync(0xffffffffu, bb, o);
            b2 += __shfl_xor_sync(0xffffffffu, b2, o);
        }
        if (lane == 0) { g_S[0] = bb * invD; g_S[1] = b2 * invD; }
    }
}

// ============================================================
// Fused: cp.async C pipeline, FFMA2 matvec, 3 blocks/SM
// ============================================================
__global__ __launch_bounds__(256, 3)
void fused_kernel(const float* __restrict__ x,
                  const float* __restrict__ C,
                  const unsigned char* __restrict__ mask,
                  const float* __restrict__ W,
                  const float* __restrict__ bias,
                  const float* __restrict__ gamma,
                  const float* __restrict__ beta,
                  const float* __restrict__ gatep,
                  const float* __restrict__ centers,
                  const float* __restrict__ widths,
                  float* __restrict__ out)
{
    extern __shared__ float sC[];             // [2][8192]

    const int tid  = threadIdx.x;
    const int lane = tid & 31;
    const int wid  = tid >> 5;
    const int d0   = tid * 2;
    const float gate = *gatep;

    __shared__ float sG[FEAT * GPITCH];
    __shared__ float sH[FEAT], sWb[FEAT], sS[2];
    __shared__ float sCW[2 * NRBF];
    __shared__ __align__(16) float zdup[8][2 * FEAT];   // (z,z) pairs per row
    __shared__ __align__(16) float msg[8][4];           // mu, grs, g, pad

    for (int i = tid; i < FEAT * FEAT; i += 256)
        sG[(i / FEAT) * GPITCH + (i % FEAT)] = g_G[i];
    if (tid < FEAT)  { sH[tid] = g_H[tid]; sWb[tid] = g_Wbar[tid]; }
    if (tid < 2)       sS[tid] = g_S[tid];
    if (tid < NRBF)  { sCW[tid] = centers[tid]; sCW[NRBF + tid] = widths[tid]; }
    if (tid < 8)       msg[tid][3] = 0.f;

    // packed weight slice: w2[f] = (W[f][d0], W[f][d0+1])
    uint64_t w2[FEAT];
#pragma unroll
    for (int f = 0; f < FEAT; f++) {
        const float2 ww = *reinterpret_cast<const float2*>(W + f * DDIM + d0);
        w2[f] = packf2(ww.x, ww.y);
    }
    const float2 bbv = *reinterpret_cast<const float2*>(bias  + d0);
    const uint64_t pbias = packf2(bbv.x, bbv.y);
    const float2 gg = *reinterpret_cast<const float2*>(gamma + d0);
    const float2 be = *reinterpret_cast<const float2*>(beta  + d0);

    const int step = gridDim.x * 8;
    int base = blockIdx.x * 8;

    // ---- prologue: async-copy C tile 0 (contiguous 8 rows) ----
    if (base < NROWS) {
        const float* gC = C + (size_t)base * SDIM;
#pragma unroll
        for (int k = 0; k < 8; k++) cp16(sC + (tid + 256 * k) * 4, gC + (tid + 256 * k) * 4);
        asm volatile("cp.async.commit_group;" ::: "memory");
    }

    int buf = 0;
    for (; base < NROWS; base += step, buf ^= 1) {
        const int nb = base + step;
        if (nb < NROWS) {
            float* dC = sC + (buf ^ 1) * SM_C_FLOATS;
            const float* gC = C + (size_t)nb * SDIM;
#pragma unroll
            for (int k = 0; k < 8; k++) cp16(dC + (tid + 256 * k) * 4, gC + (tid + 256 * k) * 4);
            asm volatile("cp.async.commit_group;" ::: "memory");
            asm volatile("cp.async.wait_group 1;" ::: "memory");
        } else {
            asm volatile("cp.async.wait_group 0;" ::: "memory");
        }
        __syncthreads();   // tile[buf] visible to all warps

        const int myrow = base + wid;

        // ---- phase 1: warp-per-row stats from smem ----
        const float4* cp4 = reinterpret_cast<const float4*>(sC + buf * SM_C_FLOATS + wid * SDIM);
        float s = 0.f, s2 = 0.f, mn = 1e30f, mx = -1e30f;
#pragma unroll
        for (int h = 0; h < 2; h++) {
            float4 v[4];
#pragma unroll
            for (int k = 0; k < 4; k++) v[k] = cp4[lane + 32 * (4 * h + k)];
#pragma unroll
            for (int k = 0; k < 4; k++) {
                const float a0 = fminf(fmaxf(v[k].x, 0.f), 1.f);
                const float a1 = fminf(fmaxf(v[k].y, 0.f), 1.f);
                const float a2 = fminf(fmaxf(v[k].z, 0.f), 1.f);
                const float a3 = fminf(fmaxf(v[k].w, 0.f), 1.f);
                s  += (a0 + a1) + (a2 + a3);
                s2  = fmaf(a0, a0, fmaf(a1, a1, fmaf(a2, a2, fmaf(a3, a3, s2))));
                mn  = fminf(mn, fminf(fminf(a0, a1), fminf(a2, a3)));
                mx  = fmaxf(mx, fmaxf(fmaxf(a0, a1), fmaxf(a2, a3)));
            }
        }
#pragma unroll
        for (int o = 16; o; o >>= 1) {
            s  += __shfl_xor_sync(0xffffffffu, s,  o);
            s2 += __shfl_xor_sync(0xffffffffu, s2, o);
            mn  = fminf(mn, __shfl_xor_sync(0xffffffffu, mn, o));
            mx  = fmaxf(mx, __shfl_xor_sync(0xffffffffu, mx, o));
        }
        const float mean = s  * (1.f / SDIM);
        const float m2   = s2 * (1.f / SDIM);
        const float sd   = sqrtf(fmaxf(m2 - mean * mean, 0.f));

        float zl = 0.f;
        if (lane < FEAT) {
            if      (lane == 0) zl = mean;
            else if (lane == 1) zl = mx;
            else if (lane == 2) zl = mn;
            else if (lane == 3) zl = sd;
            else {
                const float v0 = (lane < 4 + NRBF) ? mean : mx;
                const int   ci = (lane < 4 + NRBF) ? (lane - 4) : (lane - 4 - NRBF);
                const float dd = (v0 - sCW[ci]) / (sCW[NRBF + ci] + 1e-6f);
                zl = __expf(-0.5f * dd * dd);
            }
            // duplicated pair for FFMA2 consumption
            *reinterpret_cast<float2*>(&zdup[wid][lane * 2]) = make_float2(zl, zl);
        }
        __syncwarp();

        // ---- analytic LN: mu = z.wbar + bbar ; E2 = z'Gz + 2 z.h + mean(b^2) ----
        float q = 0.f, m = 0.f;
        if (lane < FEAT) {
            float gz = 0.f;
#pragma unroll
            for (int j = 0; j < FEAT; j++)
                gz = fmaf(sG[lane * GPITCH + j], zdup[wid][2 * j], gz);
            q = zl * fmaf(2.f, sH[lane], gz);
            m = zl * sWb[lane];
        }
#pragma unroll
        for (int o = 16; o; o >>= 1) {
            q += __shfl_xor_sync(0xffffffffu, q, o);
            m += __shfl_xor_sync(0xffffffffu, m, o);
        }
        if (lane == 0) {
            const float mu  = m + sS[0];
            const float var = fmaxf(q + sS[1] - mu * mu, 0.f);
            const float g   = mask[myrow] ? 0.f : gate;
            msg[wid][0] = mu;
            msg[wid][1] = g * rsqrtf(var + 1e-5f);
            msg[wid][2] = g;
        }
        __syncthreads();   // A: all 8 rows ready

        // ---- phase 2: FFMA2 matvec + LN apply + residual, 8 rows ----
#pragma unroll
        for (int r = 0; r < 8; r++) {
            const ulonglong2* zp = reinterpret_cast<const ulonglong2*>(zdup[r]);
            uint64_t p = pbias;
#pragma unroll
            for (int f2 = 0; f2 < FEAT / 2; f2++) {
                const ulonglong2 zz = zp[f2];
                asm("fma.rn.f32x2 %0, %1, %2, %0;" : "+l"(p) : "l"(zz.x), "l"(w2[2 * f2]));
                asm("fma.rn.f32x2 %0, %1, %2, %0;" : "+l"(p) : "l"(zz.y), "l"(w2[2 * f2 + 1]));
            }
            float p0, p1;
            asm("mov.b64 {%0, %1}, %2;" : "=f"(p0), "=f"(p1) : "l"(p));

            const float4 m4 = *reinterpret_cast<const float4*>(msg[r]);
            const float mu = m4.x, grs = m4.y, g = m4.z;

            const float2 xx = __ldcs(reinterpret_cast<const float2*>(
                                     x + (size_t)(base + r) * DDIM + d0));
            const float o0 = fmaf(grs * gg.x, p0 - mu, fmaf(g, be.x, xx.x));
            const float o1 = fmaf(grs * gg.y, p1 - mu, fmaf(g, be.y, xx.y));
            __stcs(reinterpret_cast<float2*>(out + (size_t)(base + r) * DDIM + d0),
                   make_float2(o0, o1));
        }
        __syncthreads();   // B: buf + zdup/msg safe to overwrite
    }
}

extern "C" void kernel_launch(void* const* d_in, const int* in_sizes, int n_in,
                              void* d_out, int out_size)
{
    const float*         x       = (const float*)d_in[0];
    const float*         C       = (const float*)d_in[1];
    const unsigned char* mask    = (const unsigned char*)d_in[2];
    const float*         W       = (const float*)d_in[3];
    const float*         bias    = (const float*)d_in[4];
    const float*         gamma   = (const float*)d_in[5];
    const float*         beta    = (const float*)d_in[6];
    const float*         gate    = (const float*)d_in[7];
    const float*         centers = (const float*)d_in[8];
    const float*         widths  = (const float*)d_in[9];
    float*               out     = (float*)d_out;

    static bool attr_set = false;
    if (!attr_set) {
        cudaFuncSetAttribute(fused_kernel,
                             cudaFuncAttributeMaxDynamicSharedMemorySize, DSMEM_BYTES);
        attr_set = true;
    }

    k0_precompute<<<53, 256>>>(W, bias);
    fused_kernel<<<444, 256, DSMEM_BYTES>>>(x, C, mask, W, bias, gamma, beta,
                                            gate, centers, widths, out);
}

// round 7
// speedup vs baseline: 1.2271x; 1.2271x over previous
#include <cuda_runtime.h>
#include <cuda_bf16.h>
#include <cstdint>

#define NROWS 100000
#define SDIM  1024
#define DDIM  512
#define NRBF  8
#define FEAT  20
#define GPITCH 21

// dynamic smem layout (floats): C double buf 2*8192, x double buf 2*4096
#define SM_C_FLOATS 8192
#define SM_X_FLOATS 4096
#define DSMEM_BYTES ((2 * SM_C_FLOATS + 2 * SM_X_FLOATS) * 4)   // 98304

__device__ float g_G[FEAT * FEAT];
__device__ float g_H[FEAT];
__device__ float g_Wbar[FEAT];
__device__ float g_S[2];

__device__ __forceinline__ void cp16(void* dst, const void* src) {
    unsigned d = (unsigned)__cvta_generic_to_shared(dst);
    asm volatile("cp.async.cg.shared.global [%0], [%1], 16;" :: "r"(d), "l"(src));
}
__device__ __forceinline__ uint64_t packf2(float lo, float hi) {
    uint64_t r;
    asm("mov.b64 %0, {%1, %2};" : "=l"(r) : "f"(lo), "f"(hi));
    return r;
}

// ============================================================
// K0: warp-per-item precompute (421 items)
// ============================================================
__global__ void k0_precompute(const float* __restrict__ W,
                              const float* __restrict__ b)
{
    const int lane = threadIdx.x & 31;
    const int item = (blockIdx.x * blockDim.x + threadIdx.x) >> 5;
    const float invD = 1.0f / DDIM;

    if (item < FEAT * FEAT) {
        const int l = item / FEAT, m = item % FEAT;
        const float4* wl = reinterpret_cast<const float4*>(W + l * DDIM);
        const float4* wm = reinterpret_cast<const float4*>(W + m * DDIM);
        float s = 0.f;
#pragma unroll
        for (int k = 0; k < 4; k++) {
            const float4 a = wl[lane + 32 * k];
            const float4 c = wm[lane + 32 * k];
            s = fmaf(a.x, c.x, fmaf(a.y, c.y, fmaf(a.z, c.z, fmaf(a.w, c.w, s))));
        }
#pragma unroll
        for (int o = 16; o; o >>= 1) s += __shfl_xor_sync(0xffffffffu, s, o);
        if (lane == 0) g_G[item] = s * invD;
    } else if (item < FEAT * FEAT + FEAT) {
        const int l = item - FEAT * FEAT;
        const float4* wl = reinterpret_cast<const float4*>(W + l * DDIM);
        const float4* bp = reinterpret_cast<const float4*>(b);
        float h = 0.f, wb = 0.f;
#pragma unroll
        for (int k = 0; k < 4; k++) {
            const float4 a = wl[lane + 32 * k];
            const float4 c = bp[lane + 32 * k];
            h  = fmaf(a.x, c.x, fmaf(a.y, c.y, fmaf(a.z, c.z, fmaf(a.w, c.w, h))));
            wb += (a.x + a.y) + (a.z + a.w);
        }
#pragma unroll
        for (int o = 16; o; o >>= 1) {
            h  += __shfl_xor_sync(0xffffffffu, h,  o);
            wb += __shfl_xor_sync(0xffffffffu, wb, o);
        }
        if (lane == 0) { g_H[l] = h * invD; g_Wbar[l] = wb * invD; }
    } else if (item == FEAT * FEAT + FEAT) {
        const float4* bp = reinterpret_cast<const float4*>(b);
        float bb = 0.f, b2 = 0.f;
#pragma unroll
        for (int k = 0; k < 4; k++) {
            const float4 c = bp[lane + 32 * k];
            bb += (c.x + c.y) + (c.z + c.w);
            b2  = fmaf(c.x, c.x, fmaf(c.y, c.y, fmaf(c.z, c.z, fmaf(c.w, c.w, b2))));
        }
#pragma unroll
        for (int o = 16; o; o >>= 1) {
            bb += __shfl_xor_sync(0xffffffffu, bb, o);
            b2 += __shfl_xor_sync(0xffffffffu, b2, o);
        }
        if (lane == 0) { g_S[0] = bb * invD; g_S[1] = b2 * invD; }
    }
}

// ============================================================
// Fused: R5 cp.async C+x pipeline + FFMA2 matvec
// ============================================================
__global__ __launch_bounds__(256)
void fused_kernel(const float* __restrict__ x,
                  const float* __restrict__ C,
                  const unsigned char* __restrict__ mask,
                  const float* __restrict__ W,
                  const float* __restrict__ bias,
                  const float* __restrict__ gamma,
                  const float* __restrict__ beta,
                  const float* __restrict__ gatep,
                  const float* __restrict__ centers,
                  const float* __restrict__ widths,
                  float* __restrict__ out)
{
    extern __shared__ float dsm[];
    float* sC = dsm;                          // [2][8192]
    float* sX = dsm + 2 * SM_C_FLOATS;        // [2][4096]

    const int tid  = threadIdx.x;
    const int lane = tid & 31;
    const int wid  = tid >> 5;
    const int d0   = tid * 2;
    const float gate = *gatep;

    __shared__ float sG[FEAT * GPITCH];
    __shared__ float sH[FEAT], sWb[FEAT], sS[2];
    __shared__ float sCW[2 * NRBF];
    __shared__ __align__(16) float zdup[8][2 * FEAT];   // (z,z) pairs per row
    __shared__ __align__(16) float msg[8][4];           // mu, grs, g, pad

    for (int i = tid; i < FEAT * FEAT; i += 256)
        sG[(i / FEAT) * GPITCH + (i % FEAT)] = g_G[i];
    if (tid < FEAT)  { sH[tid] = g_H[tid]; sWb[tid] = g_Wbar[tid]; }
    if (tid < 2)       sS[tid] = g_S[tid];
    if (tid < NRBF)  { sCW[tid] = centers[tid]; sCW[NRBF + tid] = widths[tid]; }
    if (tid < 8)       msg[tid][3] = 0.f;

    // packed weight slice: w2[f] = (W[f][d0], W[f][d0+1])
    uint64_t w2[FEAT];
#pragma unroll
    for (int f = 0; f < FEAT; f++) {
        const float2 ww = *reinterpret_cast<const float2*>(W + f * DDIM + d0);
        w2[f] = packf2(ww.x, ww.y);
    }
    const float2 bbv = *reinterpret_cast<const float2*>(bias  + d0);
    const uint64_t pbias = packf2(bbv.x, bbv.y);
    const float2 gg = *reinterpret_cast<const float2*>(gamma + d0);
    const float2 be = *reinterpret_cast<const float2*>(beta  + d0);

    const int step = gridDim.x * 8;
    int base = blockIdx.x * 8;

    // ---- prologue: async-copy tile 0 (contiguous 8 rows) ----
    if (base < NROWS) {
        const float* gC = C + (size_t)base * SDIM;
        const float* gx = x + (size_t)base * DDIM;
#pragma unroll
        for (int k = 0; k < 8; k++) cp16(sC + (tid + 256 * k) * 4, gC + (tid + 256 * k) * 4);
#pragma unroll
        for (int k = 0; k < 4; k++) cp16(sX + (tid + 256 * k) * 4, gx + (tid + 256 * k) * 4);
        asm volatile("cp.async.commit_group;" ::: "memory");
    }

    int buf = 0;
    for (; base < NROWS; base += step, buf ^= 1) {
        const int nb = base + step;
        if (nb < NROWS) {
            float* dC = sC + (buf ^ 1) * SM_C_FLOATS;
            float* dX = sX + (buf ^ 1) * SM_X_FLOATS;
            const float* gC = C + (size_t)nb * SDIM;
            const float* gx = x + (size_t)nb * DDIM;
#pragma unroll
            for (int k = 0; k < 8; k++) cp16(dC + (tid + 256 * k) * 4, gC + (tid + 256 * k) * 4);
#pragma unroll
            for (int k = 0; k < 4; k++) cp16(dX + (tid + 256 * k) * 4, gx + (tid + 256 * k) * 4);
            asm volatile("cp.async.commit_group;" ::: "memory");
            asm volatile("cp.async.wait_group 1;" ::: "memory");
        } else {
            asm volatile("cp.async.wait_group 0;" ::: "memory");
        }
        __syncthreads();   // tile[buf] resident for all warps

        const int myrow = base + wid;

        // ---- phase 1: warp-per-row stats from smem ----
        const float4* cp4 = reinterpret_cast<const float4*>(sC + buf * SM_C_FLOATS + wid * SDIM);
        float s = 0.f, s2 = 0.f, mn = 1e30f, mx = -1e30f;
#pragma unroll
        for (int h = 0; h < 2; h++) {
            float4 v[4];
#pragma unroll
            for (int k = 0; k < 4; k++) v[k] = cp4[lane + 32 * (4 * h + k)];
#pragma unroll
            for (int k = 0; k < 4; k++) {
                const float a0 = fminf(fmaxf(v[k].x, 0.f), 1.f);
                const float a1 = fminf(fmaxf(v[k].y, 0.f), 1.f);
                const float a2 = fminf(fmaxf(v[k].z, 0.f), 1.f);
                const float a3 = fminf(fmaxf(v[k].w, 0.f), 1.f);
                s  += (a0 + a1) + (a2 + a3);
                s2  = fmaf(a0, a0, fmaf(a1, a1, fmaf(a2, a2, fmaf(a3, a3, s2))));
                mn  = fminf(mn, fminf(fminf(a0, a1), fminf(a2, a3)));
                mx  = fmaxf(mx, fmaxf(fmaxf(a0, a1), fmaxf(a2, a3)));
            }
        }
#pragma unroll
        for (int o = 16; o; o >>= 1) {
            s  += __shfl_xor_sync(0xffffffffu, s,  o);
            s2 += __shfl_xor_sync(0xffffffffu, s2, o);
            mn  = fminf(mn, __shfl_xor_sync(0xffffffffu, mn, o));
            mx  = fmaxf(mx, __shfl_xor_sync(0xffffffffu, mx, o));
        }
        const float mean = s  * (1.f / SDIM);
        const float m2   = s2 * (1.f / SDIM);
        const float sd   = sqrtf(fmaxf(m2 - mean * mean, 0.f));

        float zl = 0.f;
        if (lane < FEAT) {
            if      (lane == 0) zl = mean;
            else if (lane == 1) zl = mx;
            else if (lane == 2) zl = mn;
            else if (lane == 3) zl = sd;
            else {
                const float v0 = (lane < 4 + NRBF) ? mean : mx;
                const int   ci = (lane < 4 + NRBF) ? (lane - 4) : (lane - 4 - NRBF);
                const float dd = (v0 - sCW[ci]) / (sCW[NRBF + ci] + 1e-6f);
                zl = __expf(-0.5f * dd * dd);
            }
            // duplicated pair for FFMA2 consumption
            *reinterpret_cast<float2*>(&zdup[wid][lane * 2]) = make_float2(zl, zl);
        }
        __syncwarp();

        // ---- analytic LN: mu = z.wbar + bbar ; E2 = z'Gz + 2 z.h + mean(b^2) ----
        float q = 0.f, m = 0.f;
        if (lane < FEAT) {
            float gz = 0.f;
#pragma unroll
            for (int j = 0; j < FEAT; j++)
                gz = fmaf(sG[lane * GPITCH + j], zdup[wid][2 * j], gz);
            q = zl * fmaf(2.f, sH[lane], gz);
            m = zl * sWb[lane];
        }
#pragma unroll
        for (int o = 16; o; o >>= 1) {
            q += __shfl_xor_sync(0xffffffffu, q, o);
            m += __shfl_xor_sync(0xffffffffu, m, o);
        }
        if (lane == 0) {
            const float mu  = m + sS[0];
            const float var = fmaxf(q + sS[1] - mu * mu, 0.f);
            const float g   = mask[myrow] ? 0.f : gate;
            msg[wid][0] = mu;
            msg[wid][1] = g * rsqrtf(var + 1e-5f);
            msg[wid][2] = g;
        }
        __syncthreads();   // A: all 8 rows ready

        // ---- phase 2: FFMA2 matvec + LN apply + residual, 8 rows ----
        const float* xb = sX + buf * SM_X_FLOATS;
#pragma unroll
        for (int r = 0; r < 8; r++) {
            const ulonglong2* zp = reinterpret_cast<const ulonglong2*>(zdup[r]);
            uint64_t p = pbias;
#pragma unroll
            for (int f2 = 0; f2 < FEAT / 2; f2++) {
                const ulonglong2 zz = zp[f2];
                asm("fma.rn.f32x2 %0, %1, %2, %0;" : "+l"(p) : "l"(zz.x), "l"(w2[2 * f2]));
                asm("fma.rn.f32x2 %0, %1, %2, %0;" : "+l"(p) : "l"(zz.y), "l"(w2[2 * f2 + 1]));
            }
            float p0, p1;
            asm("mov.b64 {%0, %1}, %2;" : "=f"(p0), "=f"(p1) : "l"(p));

            const float4 m4 = *reinterpret_cast<const float4*>(msg[r]);
            const float mu = m4.x, grs = m4.y, g = m4.z;

            const float2 xx = *reinterpret_cast<const float2*>(xb + r * DDIM + d0);
            const float o0 = fmaf(grs * gg.x, p0 - mu, fmaf(g, be.x, xx.x));
            const float o1 = fmaf(grs * gg.y, p1 - mu, fmaf(g, be.y, xx.y));
            *reinterpret_cast<float2*>(out + (size_t)(base + r) * DDIM + d0) =
                make_float2(o0, o1);
        }
        __syncthreads();   // B: buf + zdup/msg safe to overwrite
    }
}

extern "C" void kernel_launch(void* const* d_in, const int* in_sizes, int n_in,
                              void* d_out, int out_size)
{
    const float*         x       = (const float*)d_in[0];
    const float*         C       = (const float*)d_in[1];
    const unsigned char* mask    = (const unsigned char*)d_in[2];
    const float*         W       = (const float*)d_in[3];
    const float*         bias    = (const float*)d_in[4];
    const float*         gamma   = (const float*)d_in[5];
    const float*         beta    = (const float*)d_in[6];
    const float*         gate    = (const float*)d_in[7];
    const float*         centers = (const float*)d_in[8];
    const float*         widths  = (const float*)d_in[9];
    float*               out     = (float*)d_out;

    static bool attr_set = false;
    if (!attr_set) {
        cudaFuncSetAttribute(fused_kernel,
                             cudaFuncAttributeMaxDynamicSharedMemorySize, DSMEM_BYTES);
        attr_set = true;
    }

    k0_precompute<<<53, 256>>>(W, bias);
    fused_kernel<<<296, 256, DSMEM_BYTES>>>(x, C, mask, W, bias, gamma, beta,
                                            gate, centers, widths, out);
}

// round 8
// speedup vs baseline: 1.2786x; 1.0420x over previous
#include <cuda_runtime.h>
#include <cuda_bf16.h>
#include <cstdint>

#define NROWS 100000
#define SDIM  1024
#define DDIM  512
#define NRBF  8
#define FEAT  20
#define GPITCH 21
#define TROWS 5

// dynamic smem layout (floats): C double buf 2*5120, x double buf 2*2560
#define SM_C_FLOATS (TROWS * SDIM)            // 5120
#define SM_X_FLOATS (TROWS * DDIM)            // 2560
#define DSMEM_BYTES ((2 * SM_C_FLOATS + 2 * SM_X_FLOATS) * 4)   // 61440

__device__ float g_G[FEAT * FEAT];
__device__ float g_H[FEAT];
__device__ float g_Wbar[FEAT];
__device__ float g_S[2];

__device__ __forceinline__ void cp16(void* dst, const void* src) {
    unsigned d = (unsigned)__cvta_generic_to_shared(dst);
    asm volatile("cp.async.cg.shared.global [%0], [%1], 16;" :: "r"(d), "l"(src));
}

// ============================================================
// K0: warp-per-item precompute (421 items)
// ============================================================
__global__ void k0_precompute(const float* __restrict__ W,
                              const float* __restrict__ b)
{
    const int lane = threadIdx.x & 31;
    const int item = (blockIdx.x * blockDim.x + threadIdx.x) >> 5;
    const float invD = 1.0f / DDIM;

    if (item < FEAT * FEAT) {
        const int l = item / FEAT, m = item % FEAT;
        const float4* wl = reinterpret_cast<const float4*>(W + l * DDIM);
        const float4* wm = reinterpret_cast<const float4*>(W + m * DDIM);
        float s = 0.f;
#pragma unroll
        for (int k = 0; k < 4; k++) {
            const float4 a = wl[lane + 32 * k];
            const float4 c = wm[lane + 32 * k];
            s = fmaf(a.x, c.x, fmaf(a.y, c.y, fmaf(a.z, c.z, fmaf(a.w, c.w, s))));
        }
#pragma unroll
        for (int o = 16; o; o >>= 1) s += __shfl_xor_sync(0xffffffffu, s, o);
        if (lane == 0) g_G[item] = s * invD;
    } else if (item < FEAT * FEAT + FEAT) {
        const int l = item - FEAT * FEAT;
        const float4* wl = reinterpret_cast<const float4*>(W + l * DDIM);
        const float4* bp = reinterpret_cast<const float4*>(b);
        float h = 0.f, wb = 0.f;
#pragma unroll
        for (int k = 0; k < 4; k++) {
            const float4 a = wl[lane + 32 * k];
            const float4 c = bp[lane + 32 * k];
            h  = fmaf(a.x, c.x, fmaf(a.y, c.y, fmaf(a.z, c.z, fmaf(a.w, c.w, h))));
            wb += (a.x + a.y) + (a.z + a.w);
        }
#pragma unroll
        for (int o = 16; o; o >>= 1) {
            h  += __shfl_xor_sync(0xffffffffu, h,  o);
            wb += __shfl_xor_sync(0xffffffffu, wb, o);
        }
        if (lane == 0) { g_H[l] = h * invD; g_Wbar[l] = wb * invD; }
    } else if (item == FEAT * FEAT + FEAT) {
        const float4* bp = reinterpret_cast<const float4*>(b);
        float bb = 0.f, b2 = 0.f;
#pragma unroll
        for (int k = 0; k < 4; k++) {
            const float4 c = bp[lane + 32 * k];
            bb += (c.x + c.y) + (c.z + c.w);
            b2  = fmaf(c.x, c.x, fmaf(c.y, c.y, fmaf(c.z, c.z, fmaf(c.w, c.w, b2))));
        }
#pragma unroll
        for (int o = 16; o; o >>= 1) {
            bb += __shfl_xor_sync(0xffffffffu, bb, o);
            b2 += __shfl_xor_sync(0xffffffffu, b2, o);
        }
        if (lane == 0) { g_S[0] = bb * invD; g_S[1] = b2 * invD; }
    }
}

// ============================================================
// Fused: R5 pipeline, 5-row tiles, 3 blocks/SM
// ============================================================
__global__ __launch_bounds__(256, 3)
void fused_kernel(const float* __restrict__ x,
                  const float* __restrict__ C,
                  const unsigned char* __restrict__ mask,
                  const float* __restrict__ W,
                  const float* __restrict__ bias,
                  const float* __restrict__ gamma,
                  const float* __restrict__ beta,
                  const float* __restrict__ gatep,
                  const float* __restrict__ centers,
                  const float* __restrict__ widths,
                  float* __restrict__ out)
{
    extern __shared__ float dsm[];
    float* sC = dsm;                          // [2][5120]
    float* sX = dsm + 2 * SM_C_FLOATS;        // [2][2560]

    const int tid  = threadIdx.x;
    const int lane = tid & 31;
    const int wid  = tid >> 5;
    const int d0   = tid * 2;
    const float gate = *gatep;

    __shared__ float sG[FEAT * GPITCH];
    __shared__ float sH[FEAT], sWb[FEAT], sS[2];
    __shared__ float sCW[2 * NRBF];
    __shared__ __align__(16) float zmu[TROWS][24];

    for (int i = tid; i < FEAT * FEAT; i += 256)
        sG[(i / FEAT) * GPITCH + (i % FEAT)] = g_G[i];
    if (tid < FEAT)  { sH[tid] = g_H[tid]; sWb[tid] = g_Wbar[tid]; }
    if (tid < 2)       sS[tid] = g_S[tid];
    if (tid < NRBF)  { sCW[tid] = centers[tid]; sCW[NRBF + tid] = widths[tid]; }
    if (tid < TROWS)   zmu[tid][23] = 0.f;

    float w[FEAT][2];
#pragma unroll
    for (int f = 0; f < FEAT; f++) {
        const float2 ww = *reinterpret_cast<const float2*>(W + f * DDIM + d0);
        w[f][0] = ww.x; w[f][1] = ww.y;
    }
    const float2 bb = *reinterpret_cast<const float2*>(bias  + d0);
    const float2 gg = *reinterpret_cast<const float2*>(gamma + d0);
    const float2 be = *reinterpret_cast<const float2*>(beta  + d0);

    const int step = gridDim.x * TROWS;
    int base = blockIdx.x * TROWS;

    // ---- prologue: async-copy tile 0 (contiguous rows) ----
    if (base < NROWS) {
        const int nr = min(TROWS, NROWS - base);
        const float* gC = C + (size_t)base * SDIM;
        const float* gx = x + (size_t)base * DDIM;
        for (int i = tid; i < nr * 256; i += 256) cp16(sC + i * 4, gC + i * 4);
        for (int i = tid; i < nr * 128; i += 256) cp16(sX + i * 4, gx + i * 4);
        asm volatile("cp.async.commit_group;" ::: "memory");
    }

    int buf = 0;
    for (; base < NROWS; base += step, buf ^= 1) {
        const int nr = min(TROWS, NROWS - base);
        const int nb = base + step;
        if (nb < NROWS) {
            const int nrn = min(TROWS, NROWS - nb);
            float* dC = sC + (buf ^ 1) * SM_C_FLOATS;
            float* dX = sX + (buf ^ 1) * SM_X_FLOATS;
            const float* gC = C + (size_t)nb * SDIM;
            const float* gx = x + (size_t)nb * DDIM;
            for (int i = tid; i < nrn * 256; i += 256) cp16(dC + i * 4, gC + i * 4);
            for (int i = tid; i < nrn * 128; i += 256) cp16(dX + i * 4, gx + i * 4);
            asm volatile("cp.async.commit_group;" ::: "memory");
            asm volatile("cp.async.wait_group 1;" ::: "memory");
        } else {
            asm volatile("cp.async.wait_group 0;" ::: "memory");
        }
        __syncthreads();   // tile[buf] resident

        // ---- phase 1: warps 0..nr-1, one row each ----
        if (wid < nr) {
            const int myrow = base + wid;
            const float4* cp4 = reinterpret_cast<const float4*>(sC + buf * SM_C_FLOATS + wid * SDIM);
            float s = 0.f, s2 = 0.f, mn = 1e30f, mx = -1e30f;
#pragma unroll
            for (int h = 0; h < 2; h++) {
                float4 v[4];
#pragma unroll
                for (int k = 0; k < 4; k++) v[k] = cp4[lane + 32 * (4 * h + k)];
#pragma unroll
                for (int k = 0; k < 4; k++) {
                    const float a0 = fminf(fmaxf(v[k].x, 0.f), 1.f);
                    const float a1 = fminf(fmaxf(v[k].y, 0.f), 1.f);
                    const float a2 = fminf(fmaxf(v[k].z, 0.f), 1.f);
                    const float a3 = fminf(fmaxf(v[k].w, 0.f), 1.f);
                    s  += (a0 + a1) + (a2 + a3);
                    s2  = fmaf(a0, a0, fmaf(a1, a1, fmaf(a2, a2, fmaf(a3, a3, s2))));
                    mn  = fminf(mn, fminf(fminf(a0, a1), fminf(a2, a3)));
                    mx  = fmaxf(mx, fmaxf(fmaxf(a0, a1), fmaxf(a2, a3)));
                }
            }
#pragma unroll
            for (int o = 16; o; o >>= 1) {
                s  += __shfl_xor_sync(0xffffffffu, s,  o);
                s2 += __shfl_xor_sync(0xffffffffu, s2, o);
                mn  = fminf(mn, __shfl_xor_sync(0xffffffffu, mn, o));
                mx  = fmaxf(mx, __shfl_xor_sync(0xffffffffu, mx, o));
            }
            const float mean = s  * (1.f / SDIM);
            const float m2   = s2 * (1.f / SDIM);
            const float sd   = sqrtf(fmaxf(m2 - mean * mean, 0.f));

            float zl = 0.f;
            if (lane < FEAT) {
                if      (lane == 0) zl = mean;
                else if (lane == 1) zl = mx;
                else if (lane == 2) zl = mn;
                else if (lane == 3) zl = sd;
                else {
                    const float v0 = (lane < 4 + NRBF) ? mean : mx;
                    const int   ci = (lane < 4 + NRBF) ? (lane - 4) : (lane - 4 - NRBF);
                    const float dd = (v0 - sCW[ci]) / (sCW[NRBF + ci] + 1e-6f);
                    zl = __expf(-0.5f * dd * dd);
                }
                zmu[wid][lane] = zl;
            }
            __syncwarp();

            // analytic LN: mu = z.wbar + bbar ; E2 = z'Gz + 2 z.h + mean(b^2)
            float q = 0.f, m = 0.f;
            if (lane < FEAT) {
                float gz = 0.f;
#pragma unroll
                for (int j = 0; j < FEAT; j++)
                    gz = fmaf(sG[lane * GPITCH + j], zmu[wid][j], gz);
                q = zl * fmaf(2.f, sH[lane], gz);
                m = zl * sWb[lane];
            }
#pragma unroll
            for (int o = 16; o; o >>= 1) {
                q += __shfl_xor_sync(0xffffffffu, q, o);
                m += __shfl_xor_sync(0xffffffffu, m, o);
            }
            if (lane == 0) {
                const float mu  = m + sS[0];
                const float var = fmaxf(q + sS[1] - mu * mu, 0.f);
                const float g   = mask[myrow] ? 0.f : gate;
                zmu[wid][20] = mu;
                zmu[wid][21] = g * rsqrtf(var + 1e-5f);
                zmu[wid][22] = g;
            }
        }
        __syncthreads();   // A: all nr rows ready

        // ---- phase 2: matvec + LN apply + residual ----
        const float* xb = sX + buf * SM_X_FLOATS;
#pragma unroll
        for (int r = 0; r < TROWS; r++) {
            if (r < nr) {
                float zr[24];
                const float4* sp = reinterpret_cast<const float4*>(zmu[r]);
#pragma unroll
                for (int k = 0; k < 6; k++) *reinterpret_cast<float4*>(zr + 4 * k) = sp[k];
                const float2 xx = *reinterpret_cast<const float2*>(xb + r * DDIM + d0);

                float p0 = bb.x, p1 = bb.y;
#pragma unroll
                for (int f = 0; f < FEAT; f++) {
                    p0 = fmaf(zr[f], w[f][0], p0);
                    p1 = fmaf(zr[f], w[f][1], p1);
                }
                const float mu = zr[20], grs = zr[21], g = zr[22];
                const float o0 = fmaf(grs * gg.x, p0 - mu, fmaf(g, be.x, xx.x));
                const float o1 = fmaf(grs * gg.y, p1 - mu, fmaf(g, be.y, xx.y));
                *reinterpret_cast<float2*>(out + (size_t)(base + r) * DDIM + d0) =
                    make_float2(o0, o1);
            }
        }
        __syncthreads();   // B: buf + zmu safe to overwrite
    }
}

extern "C" void kernel_launch(void* const* d_in, const int* in_sizes, int n_in,
                              void* d_out, int out_size)
{
    const float*         x       = (const float*)d_in[0];
    const float*         C       = (const float*)d_in[1];
    const unsigned char* mask    = (const unsigned char*)d_in[2];
    const float*         W       = (const float*)d_in[3];
    const float*         bias    = (const float*)d_in[4];
    const float*         gamma   = (const float*)d_in[5];
    const float*         beta    = (const float*)d_in[6];
    const float*         gate    = (const float*)d_in[7];
    const float*         centers = (const float*)d_in[8];
    const float*         widths  = (const float*)d_in[9];
    float*               out     = (float*)d_out;

    static bool attr_set = false;
    if (!attr_set) {
        cudaFuncSetAttribute(fused_kernel,
                             cudaFuncAttributeMaxDynamicSharedMemorySize, DSMEM_BYTES);
        attr_set = true;
    }

    k0_precompute<<<53, 256>>>(W, bias);
    fused_kernel<<<444, 256, DSMEM_BYTES>>>(x, C, mask, W, bias, gamma, beta,
                                            gate, centers, widths, out);
}